// round 1
// baseline (speedup 1.0000x reference)
#include <cuda_runtime.h>
#include <cstdint>

#define D 128
#define NMAX 50000

// Scratch (allocation-free rule: __device__ globals)
__device__ __align__(16) float g_h[NMAX * D];     // feature + aggregated neighbors
__device__ __align__(16) float g_y1[NMAX * D];    // hidden layer
__device__ __align__(16) float g_stats[2 * D];    // col sums / sumsq -> scale / shift

// ---------------------------------------------------------------------------
// f32x2 packed-FMA helpers (2x fp32 FMA throughput; only reachable via PTX)
// ---------------------------------------------------------------------------
__device__ __forceinline__ double pack2(float lo, float hi) {
    double d;
    asm("mov.b64 %0, {%1, %2};" : "=d"(d) : "f"(lo), "f"(hi));
    return d;
}
__device__ __forceinline__ void unpack2(double d, float& lo, float& hi) {
    asm("mov.b64 {%0, %1}, %2;" : "=f"(lo), "=f"(hi) : "d"(d));
}
__device__ __forceinline__ void fma2(double& acc, double a, double b) {
    asm("fma.rn.f32x2 %0, %1, %2, %0;" : "+d"(acc) : "d"(a), "d"(b));
}

// ---------------------------------------------------------------------------
// Kernel 1: h = feature (eps=0 -> (1+eps)*feature == feature); zero BN stats
// ---------------------------------------------------------------------------
__global__ void k_init(const float4* __restrict__ feat, int n4) {
    int i = blockIdx.x * blockDim.x + threadIdx.x;
    if (i < n4) reinterpret_cast<float4*>(g_h)[i] = feat[i];
    if (blockIdx.x == 0 && threadIdx.x < 2 * D) g_stats[threadIdx.x] = 0.0f;
}

// ---------------------------------------------------------------------------
// Kernel 2: scatter-add. One warp per edge; lane handles 4 floats.
// red.global.add.v4.f32 -> 1 REDG.128 per lane instead of 4 scalar REDs.
// ---------------------------------------------------------------------------
__global__ void k_scatter(const float* __restrict__ feat,
                          const int* __restrict__ ei, int E) {
    int gw = (blockIdx.x * blockDim.x + threadIdx.x) >> 5;
    int lane = threadIdx.x & 31;
    if (gw >= E) return;
    int src = __ldg(ei + gw);
    int dst = __ldg(ei + E + gw);
    const float4 v = reinterpret_cast<const float4*>(feat + (size_t)src * D)[lane];
    float* p = g_h + (size_t)dst * D + lane * 4;
    asm volatile("red.global.add.v4.f32 [%0], {%1, %2, %3, %4};"
                 :: "l"(p), "f"(v.x), "f"(v.y), "f"(v.z), "f"(v.w)
                 : "memory");
}

// ---------------------------------------------------------------------------
// Kernel 3/4: C = relu(A @ W + b), A [M,128], W [128,128].
// BM=128, BN=128 (full width), BK=16, 256 threads (16x16), 8x8 per thread.
// Rows paired into f32x2 accumulators: A pairs load directly as double2 from
// SMEM (row-contiguous layout As[k][row]); B values broadcast-packed.
// STATS=true additionally accumulates per-column sum / sumsq for BatchNorm.
// ---------------------------------------------------------------------------
template <bool STATS>
__global__ __launch_bounds__(256, 1)
void k_gemm(const float* __restrict__ W, const float* __restrict__ bias,
            float* __restrict__ outp, int M) {
    const float* __restrict__ A = STATS ? g_y1 : g_h;
    float* __restrict__ C = STATS ? outp : g_y1;

    __shared__ __align__(16) float As[16][132];  // [k][row], padded
    __shared__ __align__(16) float Bs[16][128];  // [k][col]
    __shared__ float Red[16][128];               // stats reduction

    const int tid = threadIdx.x;
    const int tx = tid & 15;        // col group
    const int ty = tid >> 4;        // row group
    const int rowBase = blockIdx.x * 128;

    double acc[4][8];               // 4 row-pairs x 8 cols
#pragma unroll
    for (int p = 0; p < 4; ++p)
#pragma unroll
        for (int j = 0; j < 8; ++j) acc[p][j] = 0.0;

    for (int kt = 0; kt < 8; ++kt) {
        // Load A tile (128 rows x 16 k), transposed into As[k][row]
#pragma unroll
        for (int t = 0; t < 2; ++t) {
            int f = tid + t * 256;          // 0..511
            int row = f >> 2;               // 0..127
            int k4 = (f & 3) * 4;           // 0,4,8,12
            int grow = rowBase + row;
            float4 v = (grow < M)
                ? *reinterpret_cast<const float4*>(A + (size_t)grow * 128 + kt * 16 + k4)
                : make_float4(0.f, 0.f, 0.f, 0.f);
            As[k4 + 0][row] = v.x;
            As[k4 + 1][row] = v.y;
            As[k4 + 2][row] = v.z;
            As[k4 + 3][row] = v.w;
        }
        // Load B tile (16 k x 128 cols), direct copy
#pragma unroll
        for (int t = 0; t < 2; ++t) {
            int f = tid + t * 256;
            int kk = f >> 5;                // 0..15
            int c4 = (f & 31) * 4;          // 0..124
            *reinterpret_cast<float4*>(&Bs[kk][c4]) =
                *reinterpret_cast<const float4*>(W + (size_t)(kt * 16 + kk) * 128 + c4);
        }
        __syncthreads();

#pragma unroll
        for (int k = 0; k < 16; ++k) {
            double2 aA = *reinterpret_cast<const double2*>(&As[k][ty * 8]);
            double2 aB = *reinterpret_cast<const double2*>(&As[k][ty * 8 + 4]);
            float4 b0v = *reinterpret_cast<const float4*>(&Bs[k][tx * 4]);
            float4 b1v = *reinterpret_cast<const float4*>(&Bs[k][64 + tx * 4]);
            double ap[4] = {aA.x, aA.y, aB.x, aB.y};
            double bc[8] = {pack2(b0v.x, b0v.x), pack2(b0v.y, b0v.y),
                            pack2(b0v.z, b0v.z), pack2(b0v.w, b0v.w),
                            pack2(b1v.x, b1v.x), pack2(b1v.y, b1v.y),
                            pack2(b1v.z, b1v.z), pack2(b1v.w, b1v.w)};
#pragma unroll
            for (int p = 0; p < 4; ++p)
#pragma unroll
                for (int j = 0; j < 8; ++j) fma2(acc[p][j], ap[p], bc[j]);
        }
        __syncthreads();
    }

    // Epilogue: bias + relu + store (+ optional BN stats)
    float cv[8][8];
#pragma unroll
    for (int p = 0; p < 4; ++p)
#pragma unroll
        for (int j = 0; j < 8; ++j)
            unpack2(acc[p][j], cv[2 * p][j], cv[2 * p + 1][j]);

    const float4 bb0 = *reinterpret_cast<const float4*>(bias + tx * 4);
    const float4 bb1 = *reinterpret_cast<const float4*>(bias + 64 + tx * 4);
    float bj[8] = {bb0.x, bb0.y, bb0.z, bb0.w, bb1.x, bb1.y, bb1.z, bb1.w};

    float cs[8], cq[8];
#pragma unroll
    for (int j = 0; j < 8; ++j) { cs[j] = 0.f; cq[j] = 0.f; }

#pragma unroll
    for (int i = 0; i < 8; ++i) {
        int row = rowBase + ty * 8 + i;
        if (row < M) {
            float v[8];
#pragma unroll
            for (int j = 0; j < 8; ++j) v[j] = fmaxf(cv[i][j] + bj[j], 0.f);
            *reinterpret_cast<float4*>(C + (size_t)row * 128 + tx * 4) =
                make_float4(v[0], v[1], v[2], v[3]);
            *reinterpret_cast<float4*>(C + (size_t)row * 128 + 64 + tx * 4) =
                make_float4(v[4], v[5], v[6], v[7]);
            if (STATS) {
#pragma unroll
                for (int j = 0; j < 8; ++j) { cs[j] += v[j]; cq[j] += v[j] * v[j]; }
            }
        }
    }

    if (STATS) {
        __syncthreads();
#pragma unroll
        for (int j = 0; j < 8; ++j) {
            int col = (j < 4) ? tx * 4 + j : 64 + tx * 4 + (j - 4);
            Red[ty][col] = cs[j];
        }
        __syncthreads();
        if (tid < 128) {
            float s = 0.f;
#pragma unroll
            for (int t = 0; t < 16; ++t) s += Red[t][tid];
            atomicAdd(&g_stats[tid], s);
        }
        __syncthreads();
#pragma unroll
        for (int j = 0; j < 8; ++j) {
            int col = (j < 4) ? tx * 4 + j : 64 + tx * 4 + (j - 4);
            Red[ty][col] = cq[j];
        }
        __syncthreads();
        if (tid < 128) {
            float s = 0.f;
#pragma unroll
            for (int t = 0; t < 16; ++t) s += Red[t][tid];
            atomicAdd(&g_stats[128 + tid], s);
        }
    }
}

// ---------------------------------------------------------------------------
// Kernel 5: convert (sum, sumsq) -> (scale, shift). 1 block, 128 threads.
// ---------------------------------------------------------------------------
__global__ void k_finalize(const float* __restrict__ gamma,
                           const float* __restrict__ beta, float invN) {
    int c = threadIdx.x;
    float mean = g_stats[c] * invN;
    float var = g_stats[128 + c] * invN - mean * mean;
    float scale = gamma[c] * rsqrtf(var + 1e-5f);
    g_stats[c] = scale;
    g_stats[128 + c] = beta[c] - mean * scale;
}

// ---------------------------------------------------------------------------
// Kernel 6: out = out * scale[col] + shift[col], in place, float4.
// ---------------------------------------------------------------------------
__global__ void k_norm(float4* __restrict__ out, int n4) {
    int i = blockIdx.x * blockDim.x + threadIdx.x;
    if (i >= n4) return;
    int c4 = (i & 31) * 4;  // 32 float4 per 128-wide row
    float4 sc = *reinterpret_cast<const float4*>(&g_stats[c4]);
    float4 sh = *reinterpret_cast<const float4*>(&g_stats[128 + c4]);
    float4 v = out[i];
    v.x = v.x * sc.x + sh.x;
    v.y = v.y * sc.y + sh.y;
    v.z = v.z * sc.z + sh.z;
    v.w = v.w * sc.w + sh.w;
    out[i] = v;
}

// ---------------------------------------------------------------------------
extern "C" void kernel_launch(void* const* d_in, const int* in_sizes, int n_in,
                              void* d_out, int out_size) {
    const float* feat  = (const float*)d_in[0];
    const int*   ei    = (const int*)d_in[1];
    const float* W1    = (const float*)d_in[2];
    const float* b1    = (const float*)d_in[3];
    const float* W2    = (const float*)d_in[4];
    const float* b2    = (const float*)d_in[5];
    const float* gamma = (const float*)d_in[6];
    const float* beta  = (const float*)d_in[7];
    float* out = (float*)d_out;

    const int N = in_sizes[0] / D;     // 50000
    const int E = in_sizes[1] / 2;     // 600000
    const int n4 = N * D / 4;

    k_init<<<(n4 + 255) / 256, 256>>>((const float4*)feat, n4);
    {
        long long totalThreads = (long long)E * 32;
        int blocks = (int)((totalThreads + 255) / 256);
        k_scatter<<<blocks, 256>>>(feat, ei, E);
    }
    int gb = (N + 127) / 128;
    k_gemm<false><<<gb, 256>>>(W1, b1, nullptr, N);
    k_gemm<true><<<gb, 256>>>(W2, b2, out, N);
    k_finalize<<<1, 128>>>(gamma, beta, 1.0f / (float)N);
    k_norm<<<(n4 + 255) / 256, 256>>>((float4*)out, n4);
}